// round 1
// baseline (speedup 1.0000x reference)
#include <cuda_runtime.h>
#include <cstdint>

// CTRNN scan, fused input projection, cluster-resident weights.
// Shapes: B=64, T=4096, F=128, H=512, O=10, DT=0.1, all fp32.
//
// Decomposition: 16 clusters x 8 CTAs. Each cluster owns 4 batches.
// Each CTA owns a 64-column slice of W_rec (512x64 fp32, 128KB SMEM) and
// W_in (128x64 fp32, 32KB SMEM). Per step each CTA computes its 64 output
// columns for its cluster's 4 batches, then broadcasts the new state slice
// to all 8 cluster CTAs via DSMEM; one barrier.cluster per step with
// ping-pong state buffers.

#define T_STEPS   4096
#define F_IN      128
#define H_DIM     512
#define O_OUT     10
#define CLUSTER_N 8
#define NCOL      64      // H columns per CTA
#define NBATCH    4       // batches per cluster
#define NTHREADS  256
#define GRID      128     // 16 clusters * 8
#define DT_C      0.1f

struct __align__(16) Smem {
    float4 s[2][H_DIM];                 // state ping-pong: [k] -> (b0,b1,b2,b3)
    float  part[4 * NBATCH * NCOL];     // [(kq*4+b)*64 + h]
    float  xbuf[2][F_IN * NBATCH];      // [f*4 + b], ping-pong
    float  Wr[H_DIM * NCOL];            // [k*64 + h_local]
    float  Win[F_IN * NCOL];            // [f*64 + h_local]
    float  bias[NCOL];
    float  arate[NCOL];                 // DT / tau
};

__device__ __forceinline__ uint32_t smem_u32(const void* p) {
    uint32_t a;
    asm("{ .reg .u64 t; cvta.to.shared.u64 t, %1; cvt.u32.u64 %0, t; }"
        : "=r"(a) : "l"(p));
    return a;
}

__global__ void __cluster_dims__(CLUSTER_N, 1, 1) __launch_bounds__(NTHREADS, 1)
ctrnn_scan(const float* __restrict__ xg,   const float* __restrict__ ic,
           const float* __restrict__ Wing, const float* __restrict__ Wrecg,
           const float* __restrict__ bg,   const float* __restrict__ taug,
           const float* __restrict__ Rw,   const float* __restrict__ Rb,
           float* __restrict__ outg)
{
    extern __shared__ char smraw[];
    Smem* sm = reinterpret_cast<Smem*>(smraw);

    uint32_t rank;
    asm("mov.u32 %0, %%cluster_ctarank;" : "=r"(rank));
    const int tid = threadIdx.x;
    const int cl  = blockIdx.x / CLUSTER_N;     // cluster id 0..15
    const int c0  = (int)rank * NCOL;           // global column base of this CTA
    const int gb0 = cl * NBATCH;                // global batch base of this cluster

    // ---- one-time loads: weight slices, params, initial state, x[0] ----
    for (int i = tid; i < H_DIM * NCOL; i += NTHREADS)
        sm->Wr[i] = Wrecg[(i >> 6) * H_DIM + c0 + (i & 63)];
    for (int i = tid; i < F_IN * NCOL; i += NTHREADS)
        sm->Win[i] = Wing[(i >> 6) * H_DIM + c0 + (i & 63)];
    if (tid < NCOL) {
        sm->bias[tid]  = bg[c0 + tid];
        sm->arate[tid] = DT_C / taug[c0 + tid];
    }
    for (int k = tid; k < H_DIM; k += NTHREADS) {
        float v = ic[k];
        sm->s[0][k] = make_float4(v, v, v, v);
    }
    for (int i = tid; i < F_IN * NBATCH; i += NTHREADS) {
        int b = i >> 7, f = i & 127;
        sm->xbuf[0][f * NBATCH + b] = xg[((gb0 + b) * T_STEPS + 0) * F_IN + f];
    }
    __syncthreads();

    // compute-thread mapping: h = column within slice, kq = K quarter
    const int h  = tid & 63;
    const int kq = tid >> 6;
    // epilogue mapping: (eh = column, eb = batch)
    const int eh = tid & 63;
    const int eb = tid >> 6;
    const float biash = sm->bias[eh];
    const float ah    = sm->arate[eh];
    const uint32_t sbase0 = smem_u32(&sm->s[0][0]);
    const uint32_t sbase1 = smem_u32(&sm->s[1][0]);

    for (int t = 0; t < T_STEPS; t++) {
        const int cur = t & 1, nxt = cur ^ 1;

        // prefetch x[t+1] (latency hidden under the FMA loop below)
        float px0 = 0.f, px1 = 0.f;
        if (t + 1 < T_STEPS) {
            px0 = xg[((gb0 +     (tid >> 7)) * T_STEPS + t + 1) * F_IN + (tid & 127)];
            px1 = xg[((gb0 + 2 + (tid >> 7)) * T_STEPS + t + 1) * F_IN + (tid & 127)];
        }

        // ---- partial dot products: recurrent (128 k's) + input (32 f's) ----
        const float4* __restrict__ sc = sm->s[cur];
        float a0 = 0.f, a1 = 0.f, a2 = 0.f, a3 = 0.f;
        const int kb = kq * 128;
        #pragma unroll 8
        for (int kk = 0; kk < 128; kk++) {
            const float  w  = sm->Wr[(kb + kk) * NCOL + h];
            const float4 s4 = sc[kb + kk];
            a0 = fmaf(w, s4.x, a0); a1 = fmaf(w, s4.y, a1);
            a2 = fmaf(w, s4.z, a2); a3 = fmaf(w, s4.w, a3);
        }
        const int fb = kq * 32;
        const float* __restrict__ xb = sm->xbuf[cur];
        #pragma unroll 8
        for (int ff = 0; ff < 32; ff++) {
            const float  w  = sm->Win[(fb + ff) * NCOL + h];
            const float4 x4 = *reinterpret_cast<const float4*>(&xb[(fb + ff) * NBATCH]);
            a0 = fmaf(w, x4.x, a0); a1 = fmaf(w, x4.y, a1);
            a2 = fmaf(w, x4.z, a2); a3 = fmaf(w, x4.w, a3);
        }
        sm->part[(kq * NBATCH + 0) * NCOL + h] = a0;
        sm->part[(kq * NBATCH + 1) * NCOL + h] = a1;
        sm->part[(kq * NBATCH + 2) * NCOL + h] = a2;
        sm->part[(kq * NBATCH + 3) * NCOL + h] = a3;
        __syncthreads();

        // ---- epilogue: reduce 4 K-quarters, tanh, state update ----
        float sum = sm->part[(0 * NBATCH + eb) * NCOL + eh]
                  + sm->part[(1 * NBATCH + eb) * NCOL + eh]
                  + sm->part[(2 * NBATCH + eb) * NCOL + eh]
                  + sm->part[(3 * NBATCH + eb) * NCOL + eh];
        const float s_old = reinterpret_cast<const float*>(sc)[(c0 + eh) * 4 + eb];
        const float pre   = sum + biash;
        const float ns    = s_old + ah * (tanhf(pre) - s_old);

        // broadcast new state element to all 8 cluster CTAs (incl. self)
        const uint32_t laddr = (nxt ? sbase1 : sbase0)
                             + (uint32_t)(((c0 + eh) * 4 + eb) * 4);
        #pragma unroll
        for (int r = 0; r < CLUSTER_N; r++) {
            uint32_t ra;
            asm volatile("mapa.shared::cluster.u32 %0, %1, %2;"
                         : "=r"(ra) : "r"(laddr), "r"(r));
            asm volatile("st.shared::cluster.f32 [%0], %1;"
                         :: "r"(ra), "f"(ns));
        }

        // stage prefetched x for next step
        if (t + 1 < T_STEPS) {
            sm->xbuf[nxt][(tid & 127) * NBATCH +     (tid >> 7)] = px0;
            sm->xbuf[nxt][(tid & 127) * NBATCH + 2 + (tid >> 7)] = px1;
        }

        // one cluster barrier per step (release/acquire orders the DSMEM
        // stores; also acts as the block barrier for part/xbuf reuse)
        asm volatile("barrier.cluster.arrive.aligned;" ::: "memory");
        asm volatile("barrier.cluster.wait.aligned;"   ::: "memory");
    }

    // ---- readout of final state: rank-0 CTA of each cluster ----
    if (rank == 0) {
        const float* sf = reinterpret_cast<const float*>(sm->s[T_STEPS & 1]);
        const int wid = tid >> 5, lane = tid & 31;
        for (int bo = wid; bo < NBATCH * O_OUT; bo += NTHREADS / 32) {
            const int b = bo / O_OUT, o = bo % O_OUT;
            float acc = 0.f;
            for (int k = lane; k < H_DIM; k += 32)
                acc += sf[k * 4 + b] * Rw[k * O_OUT + o];
            #pragma unroll
            for (int off = 16; off; off >>= 1)
                acc += __shfl_xor_sync(0xffffffffu, acc, off);
            if (lane == 0) outg[(gb0 + b) * O_OUT + o] = acc + Rb[o];
        }
    }
}

extern "C" void kernel_launch(void* const* d_in, const int* in_sizes, int n_in,
                              void* d_out, int out_size)
{
    const float* x    = (const float*)d_in[0];  // (64,4096,128)
    const float* ic   = (const float*)d_in[1];  // (512,)
    const float* Win  = (const float*)d_in[2];  // (128,512)
    const float* Wrec = (const float*)d_in[3];  // (512,512)
    const float* b    = (const float*)d_in[4];  // (512,)
    const float* tau  = (const float*)d_in[5];  // (512,)
    const float* Rw   = (const float*)d_in[6];  // (512,10)
    const float* Rb   = (const float*)d_in[7];  // (10,)
    float* out = (float*)d_out;                 // (64,10)

    (void)in_sizes; (void)n_in; (void)out_size;

    cudaFuncSetAttribute(ctrnn_scan,
                         cudaFuncAttributeMaxDynamicSharedMemorySize,
                         (int)sizeof(Smem));
    ctrnn_scan<<<GRID, NTHREADS, sizeof(Smem)>>>(x, ic, Win, Wrec, b, tau,
                                                 Rw, Rb, out);
}

// round 3
// speedup vs baseline: 1.2186x; 1.2186x over previous
#include <cuda_runtime.h>
#include <cstdint>

// CTRNN scan: cluster-resident register weights + st.async state exchange.
// B=64, T=4096, F=128, H=512, O=10, DT=0.1, fp32.
//
// 16 clusters x 8 CTAs, 4 batches per cluster. Each CTA owns 64 output
// columns; its W_rec (512x64) and W_in (128x64) slices live in REGISTERS
// (80 floats/thread x 512 threads). Per step: f32x2 FMA mainloop over the
// SMEM state broadcast, partial reduce, tanh, then each of 128 epilogue
// threads st.async's its packed float2 into all 8 CTAs' next state buffer
// (triple-buffered), completion tracked by a tx-counting mbarrier. One
// mbarrier parity wait + one __syncthreads per step; no barrier.cluster.

#define T_STEPS   4096
#define F_IN      128
#define H_DIM     512
#define O_OUT     10
#define CLUSTER_N 8
#define NCOL      64
#define NBATCH    4
#define NTHREADS  512
#define GRID      128
#define DT_C      0.1f
#define EXPECT_BYTES 8192u   // 8 CTAs x 64 cols x 4 batches x 4B per step

typedef unsigned long long ull;

struct __align__(16) Smem {
    double2 s[3][H_DIM];        // state triple buffer: [k] = 4 packed floats
    double  part[16 * NCOL];    // [(kq*2+bp)*64 + col], packed float2
    double2 xbuf[2][F_IN];      // [f] = 4 packed floats (batch)
    ull     mbar[3];
};

__device__ __forceinline__ uint32_t smem_u32(const void* p) {
    uint32_t a;
    asm("{ .reg .u64 t; cvta.to.shared.u64 t, %1; cvt.u32.u64 %0, t; }"
        : "=r"(a) : "l"(p));
    return a;
}
__device__ __forceinline__ ull fma2(ull a, ull b, ull c) {
    ull d;
    asm("fma.rn.f32x2 %0, %1, %2, %3;" : "=l"(d) : "l"(a), "l"(b), "l"(c));
    return d;
}
__device__ __forceinline__ ull add2(ull a, ull b) {
    ull d;
    asm("add.rn.f32x2 %0, %1, %2;" : "=l"(d) : "l"(a), "l"(b));
    return d;
}
__device__ __forceinline__ ull pack2(float x) {
    ull d;
    asm("mov.b64 %0, {%1, %1};" : "=l"(d) : "f"(x));
    return d;
}
__device__ __forceinline__ ull packxy(float x, float y) {
    ull d;
    asm("mov.b64 %0, {%1, %2};" : "=l"(d) : "f"(x), "f"(y));
    return d;
}
__device__ __forceinline__ void unpack2(ull v, float& x, float& y) {
    asm("mov.b64 {%0, %1}, %2;" : "=f"(x), "=f"(y) : "l"(v));
}
__device__ __forceinline__ void mbar_wait(uint32_t m, uint32_t ph) {
    uint32_t done;
    asm volatile(
        "{\n\t.reg .pred p;\n\t"
        "mbarrier.try_wait.parity.acquire.cta.shared::cta.b64 p, [%1], %2;\n\t"
        "selp.b32 %0, 1, 0, p;\n\t}"
        : "=r"(done) : "r"(m), "r"(ph) : "memory");
    while (!done) {
        asm volatile(
            "{\n\t.reg .pred p;\n\t"
            "mbarrier.try_wait.parity.acquire.cta.shared::cta.b64 p, [%1], %2, 0x989680;\n\t"
            "selp.b32 %0, 1, 0, p;\n\t}"
            : "=r"(done) : "r"(m), "r"(ph) : "memory");
    }
}
__device__ __forceinline__ void mbar_expect(uint32_t m) {
    asm volatile("mbarrier.arrive.expect_tx.shared::cta.b64 _, [%0], %1;"
                 :: "r"(m), "r"(EXPECT_BYTES) : "memory");
}
__device__ __forceinline__ void st_async64(uint32_t daddr, ull v, uint32_t maddr) {
    asm volatile(
        "st.async.shared::cluster.mbarrier::complete_tx::bytes.b64 [%0], %1, [%2];"
        :: "r"(daddr), "l"(v), "r"(maddr) : "memory");
}
__device__ __forceinline__ uint32_t mapa_u32(uint32_t la, uint32_t r) {
    uint32_t ra;
    asm("mapa.shared::cluster.u32 %0, %1, %2;" : "=r"(ra) : "r"(la), "r"(r));
    return ra;
}

__global__ void __cluster_dims__(CLUSTER_N, 1, 1) __launch_bounds__(NTHREADS, 1)
ctrnn_scan(const float* __restrict__ xg,   const float* __restrict__ ic,
           const float* __restrict__ Wing, const float* __restrict__ Wrecg,
           const float* __restrict__ bg,   const float* __restrict__ taug,
           const float* __restrict__ Rw,   const float* __restrict__ Rb,
           float* __restrict__ outg)
{
    __shared__ Smem sm;

    uint32_t rank;
    asm("mov.u32 %0, %%cluster_ctarank;" : "=r"(rank));
    const int tid = threadIdx.x;
    const int cl  = blockIdx.x / CLUSTER_N;
    const int c0  = (int)rank * NCOL;
    const int gb0 = cl * NBATCH;

    const int h  = tid & 63;    // column within slice
    const int kq = tid >> 6;    // K eighth (0..7)

    // ---- weights to registers ----
    float w[64];
    #pragma unroll
    for (int kk = 0; kk < 64; kk++)
        w[kk] = Wrecg[(kq * 64 + kk) * H_DIM + c0 + h];
    float wi[16];
    #pragma unroll
    for (int j = 0; j < 16; j++)
        wi[j] = Wing[(kq * 16 + j) * H_DIM + c0 + h];

    // ---- epilogue-thread params & register state ----
    const int eh = tid & 63, ebp = (tid >> 6) & 1;   // valid for tid<128
    float biasv = 0.f, arv = 0.f, s0 = 0.f, s1 = 0.f;
    if (tid < 128) {
        biasv = bg[c0 + eh];
        arv   = DT_C / taug[c0 + eh];
        s0 = s1 = ic[c0 + eh];
    }

    // ---- init state buffer 0, x[0], mbarriers ----
    for (int k = tid; k < H_DIM; k += NTHREADS) {
        float v = ic[k];
        ((float4*)&sm.s[0][0])[k] = make_float4(v, v, v, v);
    }
    {
        const int b = tid >> 7, f = tid & 127;
        ((float*)&sm.xbuf[0][0])[f * 4 + b] = xg[((gb0 + b) * T_STEPS) * F_IN + f];
    }
    const uint32_t mbase = smem_u32(&sm.mbar[0]);
    const uint32_t sbase = smem_u32(&sm.s[0][0]);
    if (tid == 0) {
        #pragma unroll
        for (int i = 0; i < 3; i++) {
            asm volatile("mbarrier.init.shared::cta.b64 [%0], %1;"
                         :: "r"(mbase + i * 8), "r"(1) : "memory");
        }
        #pragma unroll
        for (int i = 0; i < 3; i++) mbar_expect(mbase + i * 8);
    }
    __syncthreads();
    // all mbarriers cluster-wide armed before any st.async
    asm volatile("barrier.cluster.arrive.aligned;" ::: "memory");
    asm volatile("barrier.cluster.wait.aligned;"   ::: "memory");

    for (int t = 0; t < T_STEPS; t++) {
        const int cur  = t % 3;
        const int nbuf = (t + 1) % 3;
        const int cx   = t & 1;

        if (t > 0) {
            const uint32_t m = mbase + (uint32_t)cur * 8u;
            mbar_wait(m, (((uint32_t)t - 1u) / 3u) & 1u);
            if (tid == 0) mbar_expect(m);   // re-arm for step t+3
        }

        // prefetch x[t+1]
        float px = 0.f;
        if (t + 1 < T_STEPS)
            px = xg[((gb0 + (tid >> 7)) * T_STEPS + t + 1) * F_IN + (tid & 127)];

        // ---- mainloop: 64 recurrent + 16 input FMAs, f32x2, reg weights ----
        const double2* __restrict__ sc = sm.s[cur];
        ull a01 = 0ull, a23 = 0ull;
        #pragma unroll
        for (int kk = 0; kk < 64; kk++) {
            const double2 v = sc[kq * 64 + kk];
            const ull ww = pack2(w[kk]);
            a01 = fma2(ww, __double_as_longlong(v.x), a01);
            a23 = fma2(ww, __double_as_longlong(v.y), a23);
        }
        const double2* __restrict__ xc = sm.xbuf[cx];
        #pragma unroll
        for (int j = 0; j < 16; j++) {
            const double2 v = xc[kq * 16 + j];
            const ull ww = pack2(wi[j]);
            a01 = fma2(ww, __double_as_longlong(v.x), a01);
            a23 = fma2(ww, __double_as_longlong(v.y), a23);
        }
        sm.part[(kq * 2 + 0) * NCOL + h] = __longlong_as_double(a01);
        sm.part[(kq * 2 + 1) * NCOL + h] = __longlong_as_double(a23);

        // stage x[t+1]
        if (t + 1 < T_STEPS)
            ((float*)&sm.xbuf[cx ^ 1][0])[(tid & 127) * 4 + (tid >> 7)] = px;

        __syncthreads();

        // ---- epilogue: reduce 8 K-eighths, tanh, update, st.async x8 ----
        if (tid < 128) {
            ull sum = __double_as_longlong(sm.part[ebp * NCOL + eh]);
            #pragma unroll
            for (int q = 1; q < 8; q++)
                sum = add2(sum, __double_as_longlong(sm.part[(q * 2 + ebp) * NCOL + eh]));
            float p0, p1;
            unpack2(sum, p0, p1);
            p0 += biasv; p1 += biasv;
            const float n0 = fmaf(arv, tanhf(p0) - s0, s0);
            const float n1 = fmaf(arv, tanhf(p1) - s1, s1);
            s0 = n0; s1 = n1;
            const ull nsp = packxy(n0, n1);

            const uint32_t doff = sbase + (uint32_t)nbuf * 8192u
                                + (uint32_t)((c0 + eh) * 16 + ebp * 8);
            const uint32_t moff = mbase + (uint32_t)nbuf * 8u;
            #pragma unroll
            for (uint32_t r = 0; r < CLUSTER_N; r++)
                st_async64(mapa_u32(doff, r), nsp, mapa_u32(moff, r));
        }
    }

    // final state: buffer T%3, armed parity ((T-1)/3)&1
    mbar_wait(mbase + (uint32_t)(T_STEPS % 3) * 8u,
              (((uint32_t)T_STEPS - 1u) / 3u) & 1u);

    if (rank == 0) {
        const float* sf = (const float*)&sm.s[T_STEPS % 3][0];
        const int wid = tid >> 5, lane = tid & 31;
        for (int bo = wid; bo < NBATCH * O_OUT; bo += NTHREADS / 32) {
            const int b = bo / O_OUT, o = bo % O_OUT;
            float acc = 0.f;
            for (int k = lane; k < H_DIM; k += 32)
                acc += sf[k * 4 + b] * Rw[k * O_OUT + o];
            #pragma unroll
            for (int off = 16; off; off >>= 1)
                acc += __shfl_xor_sync(0xffffffffu, acc, off);
            if (lane == 0) outg[(gb0 + b) * O_OUT + o] = acc + Rb[o];
        }
    }
}

extern "C" void kernel_launch(void* const* d_in, const int* in_sizes, int n_in,
                              void* d_out, int out_size)
{
    const float* x    = (const float*)d_in[0];
    const float* ic   = (const float*)d_in[1];
    const float* Win  = (const float*)d_in[2];
    const float* Wrec = (const float*)d_in[3];
    const float* b    = (const float*)d_in[4];
    const float* tau  = (const float*)d_in[5];
    const float* Rw   = (const float*)d_in[6];
    const float* Rb   = (const float*)d_in[7];
    float* out = (float*)d_out;
    (void)in_sizes; (void)n_in; (void)out_size;

    ctrnn_scan<<<GRID, NTHREADS>>>(x, ic, Win, Wrec, b, tau, Rw, Rb, out);
}

// round 4
// speedup vs baseline: 2.6365x; 2.1636x over previous
#include <cuda_runtime.h>
#include <cstdint>

// CTRNN scan: register-resident weights + bulk DSMEM state exchange.
// B=64, T=4096, F=128, H=512, O=10, DT=0.1, fp32.
//
// 16 clusters x 8 CTAs, 4 batches/cluster. Each CTA owns 64 output columns,
// weights in registers (80 f32/thread). Per step: f32x2 FMA mainloop over
// SMEM state, partial reduce + tanh.approx, epilogue writes own slice into
// the local next-state buffer, then ONE thread issues 7x 1KB
// cp.async.bulk.shared::cluster copies to the peers (tx-counted mbarrier,
// 7 updates/step instead of 1024 st.async messages). Triple-buffered state.

#define T_STEPS   4096
#define F_IN      128
#define H_DIM     512
#define O_OUT     10
#define CLUSTER_N 8
#define NCOL      64
#define NBATCH    4
#define NTHREADS  512
#define GRID      128
#define DT_C      0.1f
#define SLICE_BYTES  1024u                 // 64 cols x 4 batches x 4B
#define EXPECT_BYTES (7u * SLICE_BYTES)    // from 7 peers

typedef unsigned long long ull;

struct __align__(16) Smem {
    double2 s[3][H_DIM];        // state triple buffer: [k] = 4 packed floats
    double  part[16 * NCOL];    // [(kq*2+bp)*64 + col], packed float2
    double2 xbuf[2][F_IN];      // [f] = 4 packed floats (batch)
    ull     mbar[3];
};

__device__ __forceinline__ uint32_t smem_u32(const void* p) {
    uint32_t a;
    asm("{ .reg .u64 t; cvta.to.shared.u64 t, %1; cvt.u32.u64 %0, t; }"
        : "=r"(a) : "l"(p));
    return a;
}
__device__ __forceinline__ ull fma2(ull a, ull b, ull c) {
    ull d;
    asm("fma.rn.f32x2 %0, %1, %2, %3;" : "=l"(d) : "l"(a), "l"(b), "l"(c));
    return d;
}
__device__ __forceinline__ ull add2(ull a, ull b) {
    ull d;
    asm("add.rn.f32x2 %0, %1, %2;" : "=l"(d) : "l"(a), "l"(b));
    return d;
}
__device__ __forceinline__ ull pack2(float x) {
    ull d;
    asm("mov.b64 %0, {%1, %1};" : "=l"(d) : "f"(x));
    return d;
}
__device__ __forceinline__ ull packxy(float x, float y) {
    ull d;
    asm("mov.b64 %0, {%1, %2};" : "=l"(d) : "f"(x), "f"(y));
    return d;
}
__device__ __forceinline__ void unpack2(ull v, float& x, float& y) {
    asm("mov.b64 {%0, %1}, %2;" : "=f"(x), "=f"(y) : "l"(v));
}
__device__ __forceinline__ float tanh_fast(float x) {
    float y;
    asm("tanh.approx.f32 %0, %1;" : "=f"(y) : "f"(x));
    return y;
}
__device__ __forceinline__ void mbar_wait(uint32_t m, uint32_t ph) {
    uint32_t done;
    asm volatile(
        "{\n\t.reg .pred p;\n\t"
        "mbarrier.try_wait.parity.acquire.cta.shared::cta.b64 p, [%1], %2;\n\t"
        "selp.b32 %0, 1, 0, p;\n\t}"
        : "=r"(done) : "r"(m), "r"(ph) : "memory");
    while (!done) {
        asm volatile(
            "{\n\t.reg .pred p;\n\t"
            "mbarrier.try_wait.parity.acquire.cta.shared::cta.b64 p, [%1], %2, 0x989680;\n\t"
            "selp.b32 %0, 1, 0, p;\n\t}"
            : "=r"(done) : "r"(m), "r"(ph) : "memory");
    }
}
__device__ __forceinline__ void mbar_expect(uint32_t m) {
    asm volatile("mbarrier.arrive.expect_tx.shared::cta.b64 _, [%0], %1;"
                 :: "r"(m), "r"(EXPECT_BYTES) : "memory");
}
__device__ __forceinline__ uint32_t mapa_u32(uint32_t la, uint32_t r) {
    uint32_t ra;
    asm("mapa.shared::cluster.u32 %0, %1, %2;" : "=r"(ra) : "r"(la), "r"(r));
    return ra;
}
__device__ __forceinline__ void bulk_copy_peer(uint32_t dst, uint32_t src,
                                               uint32_t bytes, uint32_t rmbar) {
    asm volatile(
        "cp.async.bulk.shared::cluster.shared::cta.mbarrier::complete_tx::bytes "
        "[%0], [%1], %2, [%3];"
        :: "r"(dst), "r"(src), "r"(bytes), "r"(rmbar) : "memory");
}

__global__ void __cluster_dims__(CLUSTER_N, 1, 1) __launch_bounds__(NTHREADS, 1)
ctrnn_scan(const float* __restrict__ xg,   const float* __restrict__ ic,
           const float* __restrict__ Wing, const float* __restrict__ Wrecg,
           const float* __restrict__ bg,   const float* __restrict__ taug,
           const float* __restrict__ Rw,   const float* __restrict__ Rb,
           float* __restrict__ outg)
{
    __shared__ Smem sm;

    uint32_t rank;
    asm("mov.u32 %0, %%cluster_ctarank;" : "=r"(rank));
    const int tid = threadIdx.x;
    const int cl  = blockIdx.x / CLUSTER_N;
    const int c0  = (int)rank * NCOL;
    const int gb0 = cl * NBATCH;

    const int h  = tid & 63;    // column within slice
    const int kq = tid >> 6;    // K eighth (0..7)

    // ---- weights to registers ----
    float w[64];
    #pragma unroll
    for (int kk = 0; kk < 64; kk++)
        w[kk] = Wrecg[(kq * 64 + kk) * H_DIM + c0 + h];
    float wi[16];
    #pragma unroll
    for (int j = 0; j < 16; j++)
        wi[j] = Wing[(kq * 16 + j) * H_DIM + c0 + h];

    // ---- epilogue-thread params & register state ----
    const int eh = tid & 63, ebp = (tid >> 6) & 1;   // valid for tid<128
    float biasv = 0.f, arv = 0.f, s0 = 0.f, s1 = 0.f;
    if (tid < 128) {
        biasv = bg[c0 + eh];
        arv   = DT_C / taug[c0 + eh];
        s0 = s1 = ic[c0 + eh];
    }

    // ---- init state buffer 0, x[0], mbarriers ----
    for (int k = tid; k < H_DIM; k += NTHREADS) {
        float v = ic[k];
        ((float4*)&sm.s[0][0])[k] = make_float4(v, v, v, v);
    }
    {
        const int b = tid >> 7, f = tid & 127;
        ((float*)&sm.xbuf[0][0])[f * 4 + b] = xg[((gb0 + b) * T_STEPS) * F_IN + f];
    }
    const uint32_t mbase = smem_u32(&sm.mbar[0]);
    const uint32_t sbase = smem_u32(&sm.s[0][0]);
    if (tid == 0) {
        #pragma unroll
        for (int i = 0; i < 3; i++)
            asm volatile("mbarrier.init.shared::cta.b64 [%0], %1;"
                         :: "r"(mbase + i * 8), "r"(1) : "memory");
        #pragma unroll
        for (int i = 0; i < 3; i++) mbar_expect(mbase + i * 8);
    }
    __syncthreads();
    // all mbarriers cluster-wide armed before any peer copy can land
    asm volatile("barrier.cluster.arrive.aligned;" ::: "memory");
    asm volatile("barrier.cluster.wait.aligned;"   ::: "memory");

    for (int t = 0; t < T_STEPS; t++) {
        const int cur  = t % 3;
        const int nbuf = (t + 1) % 3;
        const int cx   = t & 1;

        // wait for the 7 peer slices of s[cur] (own slice ordered by the
        // post-epilogue __syncthreads of step t-1)
        if (t > 0) {
            const uint32_t m = mbase + (uint32_t)cur * 8u;
            mbar_wait(m, (((uint32_t)t - 1u) / 3u) & 1u);
            if (tid == 0) mbar_expect(m);   // re-arm for step t+3
        }

        // prefetch x[t+1]
        float px = 0.f;
        if (t + 1 < T_STEPS)
            px = xg[((gb0 + (tid >> 7)) * T_STEPS + t + 1) * F_IN + (tid & 127)];

        // ---- mainloop: 64 recurrent + 16 input FMAs, f32x2, reg weights ----
        const double2* __restrict__ sc = sm.s[cur];
        ull a01 = 0ull, a23 = 0ull;
        #pragma unroll
        for (int kk = 0; kk < 64; kk++) {
            const double2 v = sc[kq * 64 + kk];
            const ull ww = pack2(w[kk]);
            a01 = fma2(ww, __double_as_longlong(v.x), a01);
            a23 = fma2(ww, __double_as_longlong(v.y), a23);
        }
        const double2* __restrict__ xc = sm.xbuf[cx];
        #pragma unroll
        for (int j = 0; j < 16; j++) {
            const double2 v = xc[kq * 16 + j];
            const ull ww = pack2(wi[j]);
            a01 = fma2(ww, __double_as_longlong(v.x), a01);
            a23 = fma2(ww, __double_as_longlong(v.y), a23);
        }
        sm.part[(kq * 2 + 0) * NCOL + h] = __longlong_as_double(a01);
        sm.part[(kq * 2 + 1) * NCOL + h] = __longlong_as_double(a23);

        // stage x[t+1]
        if (t + 1 < T_STEPS)
            ((float*)&sm.xbuf[cx ^ 1][0])[(tid & 127) * 4 + (tid >> 7)] = px;

        __syncthreads();   // partials + xbuf visible

        // ---- epilogue: reduce, tanh, update, write own slice locally ----
        if (tid < 128) {
            ull sum = __double_as_longlong(sm.part[ebp * NCOL + eh]);
            #pragma unroll
            for (int q = 1; q < 8; q++)
                sum = add2(sum, __double_as_longlong(sm.part[(q * 2 + ebp) * NCOL + eh]));
            float p0, p1;
            unpack2(sum, p0, p1);
            const float n0 = fmaf(arv, tanh_fast(p0 + biasv) - s0, s0);
            const float n1 = fmaf(arv, tanh_fast(p1 + biasv) - s1, s1);
            s0 = n0; s1 = n1;
            // own slice element of next state buffer
            *(double*)((char*)&sm.s[nbuf][0] + (c0 + eh) * 16 + ebp * 8) =
                __longlong_as_double(packxy(n0, n1));
            // make the generic stores visible to the async (bulk-copy) proxy
            asm volatile("fence.proxy.async.shared::cta;" ::: "memory");
        }
        __syncthreads();   // slice complete + fenced before copies issue

        // ---- one thread pushes the 1KB slice to the 7 peers ----
        if (tid == 0) {
            const uint32_t src  = sbase + (uint32_t)nbuf * 8192u + (uint32_t)c0 * 16u;
            const uint32_t moff = mbase + (uint32_t)nbuf * 8u;
            #pragma unroll
            for (uint32_t r = 0; r < CLUSTER_N; r++) {
                if (r == rank) continue;
                bulk_copy_peer(mapa_u32(src, r), src, SLICE_BYTES,
                               mapa_u32(moff, r));
            }
        }
    }

    // final state: buffer T%3 (own slice via last __syncthreads, peers via wait)
    mbar_wait(mbase + (uint32_t)(T_STEPS % 3) * 8u,
              (((uint32_t)T_STEPS - 1u) / 3u) & 1u);

    if (rank == 0) {
        const float* sf = (const float*)&sm.s[T_STEPS % 3][0];
        const int wid = tid >> 5, lane = tid & 31;
        for (int bo = wid; bo < NBATCH * O_OUT; bo += NTHREADS / 32) {
            const int b = bo / O_OUT, o = bo % O_OUT;
            float acc = 0.f;
            for (int k = lane; k < H_DIM; k += 32)
                acc += sf[k * 4 + b] * Rw[k * O_OUT + o];
            #pragma unroll
            for (int off = 16; off; off >>= 1)
                acc += __shfl_xor_sync(0xffffffffu, acc, off);
            if (lane == 0) outg[(gb0 + b) * O_OUT + o] = acc + Rb[o];
        }
    }
}

extern "C" void kernel_launch(void* const* d_in, const int* in_sizes, int n_in,
                              void* d_out, int out_size)
{
    const float* x    = (const float*)d_in[0];
    const float* ic   = (const float*)d_in[1];
    const float* Win  = (const float*)d_in[2];
    const float* Wrec = (const float*)d_in[3];
    const float* b    = (const float*)d_in[4];
    const float* tau  = (const float*)d_in[5];
    const float* Rw   = (const float*)d_in[6];
    const float* Rb   = (const float*)d_in[7];
    float* out = (float*)d_out;
    (void)in_sizes; (void)n_in; (void)out_size;

    ctrnn_scan<<<GRID, NTHREADS>>>(x, ic, Win, Wrec, b, tau, Rw, Rb, out);
}

// round 5
// speedup vs baseline: 2.8130x; 1.0670x over previous
#include <cuda_runtime.h>
#include <cstdint>

// CTRNN scan: register weights + per-source-slice mbarrier dataflow.
// B=64, T=4096, F=128, H=512, O=10, DT=0.1, fp32.
//
// 16 clusters x 8 CTAs, 4 batches/cluster, 64 cols/CTA, weights in regs.
// Each warp's 64-k range maps to exactly one source rank's slice, so each
// warp waits ONLY on that slice's mbarrier (8 per state buffer: 7 tx-counted
// fed by 1KB cp.async.bulk peer copies, 1 count-based armed by the local
// epilogue). part[] ping-pong removes the second full block barrier; only
// the 4 epilogue warps run a named 128-thread barrier.

#define T_STEPS   4096
#define F_IN      128
#define H_DIM     512
#define O_OUT     10
#define CLUSTER_N 8
#define NCOL      64
#define NBATCH    4
#define NTHREADS  512
#define GRID      128
#define DT_C      0.1f
#define SLICE_BYTES 1024u   // 64 cols x 4 batches x 4B

typedef unsigned long long ull;

struct __align__(16) Smem {
    double2 s[3][H_DIM];          // state triple buffer: [k] = 4 packed floats
    double  part[2][16 * NCOL];   // ping-pong partials
    double2 xbuf[2][F_IN];
    ull     mbar[3][CLUSTER_N];   // [buffer][source rank]
};

__device__ __forceinline__ uint32_t smem_u32(const void* p) {
    uint32_t a;
    asm("{ .reg .u64 t; cvta.to.shared.u64 t, %1; cvt.u32.u64 %0, t; }"
        : "=r"(a) : "l"(p));
    return a;
}
__device__ __forceinline__ ull fma2(ull a, ull b, ull c) {
    ull d;
    asm("fma.rn.f32x2 %0, %1, %2, %3;" : "=l"(d) : "l"(a), "l"(b), "l"(c));
    return d;
}
__device__ __forceinline__ ull add2(ull a, ull b) {
    ull d;
    asm("add.rn.f32x2 %0, %1, %2;" : "=l"(d) : "l"(a), "l"(b));
    return d;
}
__device__ __forceinline__ ull pack2(float x) {
    ull d;
    asm("mov.b64 %0, {%1, %1};" : "=l"(d) : "f"(x));
    return d;
}
__device__ __forceinline__ ull packxy(float x, float y) {
    ull d;
    asm("mov.b64 %0, {%1, %2};" : "=l"(d) : "f"(x), "f"(y));
    return d;
}
__device__ __forceinline__ void unpack2(ull v, float& x, float& y) {
    asm("mov.b64 {%0, %1}, %2;" : "=f"(x), "=f"(y) : "l"(v));
}
__device__ __forceinline__ float tanh_fast(float x) {
    float y;
    asm("tanh.approx.f32 %0, %1;" : "=f"(y) : "f"(x));
    return y;
}
__device__ __forceinline__ void mbar_wait(uint32_t m, uint32_t ph) {
    uint32_t done;
    asm volatile(
        "{\n\t.reg .pred p;\n\t"
        "mbarrier.try_wait.parity.acquire.cta.shared::cta.b64 p, [%1], %2;\n\t"
        "selp.b32 %0, 1, 0, p;\n\t}"
        : "=r"(done) : "r"(m), "r"(ph) : "memory");
    while (!done) {
        asm volatile(
            "{\n\t.reg .pred p;\n\t"
            "mbarrier.try_wait.parity.acquire.cta.shared::cta.b64 p, [%1], %2, 0x989680;\n\t"
            "selp.b32 %0, 1, 0, p;\n\t}"
            : "=r"(done) : "r"(m), "r"(ph) : "memory");
    }
}
__device__ __forceinline__ void mbar_expect(uint32_t m, uint32_t bytes) {
    asm volatile("mbarrier.arrive.expect_tx.shared::cta.b64 _, [%0], %1;"
                 :: "r"(m), "r"(bytes) : "memory");
}
__device__ __forceinline__ void mbar_arrive(uint32_t m) {
    asm volatile("mbarrier.arrive.shared::cta.b64 _, [%0];"
                 :: "r"(m) : "memory");
}
__device__ __forceinline__ uint32_t mapa_u32(uint32_t la, uint32_t r) {
    uint32_t ra;
    asm("mapa.shared::cluster.u32 %0, %1, %2;" : "=r"(ra) : "r"(la), "r"(r));
    return ra;
}
__device__ __forceinline__ void bulk_copy_peer(uint32_t dst, uint32_t src,
                                               uint32_t bytes, uint32_t rmbar) {
    asm volatile(
        "cp.async.bulk.shared::cluster.shared::cta.mbarrier::complete_tx::bytes "
        "[%0], [%1], %2, [%3];"
        :: "r"(dst), "r"(src), "r"(bytes), "r"(rmbar) : "memory");
}

__global__ void __cluster_dims__(CLUSTER_N, 1, 1) __launch_bounds__(NTHREADS, 1)
ctrnn_scan(const float* __restrict__ xg,   const float* __restrict__ ic,
           const float* __restrict__ Wing, const float* __restrict__ Wrecg,
           const float* __restrict__ bg,   const float* __restrict__ taug,
           const float* __restrict__ Rw,   const float* __restrict__ Rb,
           float* __restrict__ outg)
{
    __shared__ Smem sm;

    uint32_t rank;
    asm("mov.u32 %0, %%cluster_ctarank;" : "=r"(rank));
    const int tid = threadIdx.x;
    const int cl  = blockIdx.x / CLUSTER_N;
    const int c0  = (int)rank * NCOL;
    const int gb0 = cl * NBATCH;

    const int h  = tid & 63;    // column within slice
    const int kq = tid >> 6;    // K eighth == source rank this warp consumes

    // ---- weights to registers ----
    float w[64];
    #pragma unroll
    for (int kk = 0; kk < 64; kk++)
        w[kk] = Wrecg[(kq * 64 + kk) * H_DIM + c0 + h];
    float wi[16];
    #pragma unroll
    for (int j = 0; j < 16; j++)
        wi[j] = Wing[(kq * 16 + j) * H_DIM + c0 + h];

    // ---- epilogue-thread params & register state ----
    const int eh = tid & 63, ebp = (tid >> 6) & 1;   // valid for tid<128
    float biasv = 0.f, arv = 0.f, s0 = 0.f, s1 = 0.f;
    if (tid < 128) {
        biasv = bg[c0 + eh];
        arv   = DT_C / taug[c0 + eh];
        s0 = s1 = ic[c0 + eh];
    }

    // ---- init state buffer 0, x[0], mbarriers ----
    for (int k = tid; k < H_DIM; k += NTHREADS) {
        float v = ic[k];
        ((float4*)&sm.s[0][0])[k] = make_float4(v, v, v, v);
    }
    {
        const int b = tid >> 7, f = tid & 127;
        ((float*)&sm.xbuf[0][0])[f * 4 + b] = xg[((gb0 + b) * T_STEPS) * F_IN + f];
    }
    const uint32_t mbase = smem_u32(&sm.mbar[0][0]);
    const uint32_t sbase = smem_u32(&sm.s[0][0]);
    if (tid == 0) {
        for (int n = 0; n < 3; n++)
            for (int r = 0; r < CLUSTER_N; r++) {
                const uint32_t m = mbase + (uint32_t)(n * 8 + r) * 8u;
                asm volatile("mbarrier.init.shared::cta.b64 [%0], %1;"
                             :: "r"(m), "r"(1) : "memory");
            }
        // arm all peer tx barriers once (count auto-reloads for own barriers)
        for (int n = 0; n < 3; n++)
            for (int r = 0; r < CLUSTER_N; r++)
                if (r != (int)rank)
                    mbar_expect(mbase + (uint32_t)(n * 8 + r) * 8u, SLICE_BYTES);
    }
    __syncthreads();
    // mbarriers cluster-wide visible before any peer copy can land
    asm volatile("barrier.cluster.arrive.aligned;" ::: "memory");
    asm volatile("barrier.cluster.wait.aligned;"   ::: "memory");

    for (int t = 0; t < T_STEPS; t++) {
        const int cur  = t % 3;
        const int nbuf = (t + 1) % 3;
        const int cx   = t & 1;

        // per-warp wait: only the slice this warp consumes
        if (t > 0) {
            const uint32_t m = mbase + (uint32_t)(cur * 8 + kq) * 8u;
            mbar_wait(m, (((uint32_t)t - 1u) / 3u) & 1u);
            if (tid == kq * 64 && kq != (int)rank)
                mbar_expect(m, SLICE_BYTES);        // re-arm for step t+3
        }

        // prefetch x[t+1]
        float px = 0.f;
        if (t + 1 < T_STEPS)
            px = xg[((gb0 + (tid >> 7)) * T_STEPS + t + 1) * F_IN + (tid & 127)];

        // ---- mainloop: 64 recurrent + 16 input FMAs, f32x2, reg weights ----
        const double2* __restrict__ sc = sm.s[cur];
        ull a01 = 0ull, a23 = 0ull;
        #pragma unroll
        for (int kk = 0; kk < 64; kk++) {
            const double2 v = sc[kq * 64 + kk];
            const ull ww = pack2(w[kk]);
            a01 = fma2(ww, __double_as_longlong(v.x), a01);
            a23 = fma2(ww, __double_as_longlong(v.y), a23);
        }
        const double2* __restrict__ xc = sm.xbuf[cx];
        #pragma unroll
        for (int j = 0; j < 16; j++) {
            const double2 v = xc[kq * 16 + j];
            const ull ww = pack2(wi[j]);
            a01 = fma2(ww, __double_as_longlong(v.x), a01);
            a23 = fma2(ww, __double_as_longlong(v.y), a23);
        }
        sm.part[cx][(kq * 2 + 0) * NCOL + h] = __longlong_as_double(a01);
        sm.part[cx][(kq * 2 + 1) * NCOL + h] = __longlong_as_double(a23);

        // stage x[t+1] (before the sync; read by everyone after next waits)
        if (t + 1 < T_STEPS)
            ((float*)&sm.xbuf[cx ^ 1][0])[(tid & 127) * 4 + (tid >> 7)] = px;

        __syncthreads();   // partials + staged x visible to all

        // ---- epilogue: 4 warps reduce, tanh, update, publish slice ----
        if (tid < 128) {
            ull sum = __double_as_longlong(sm.part[cx][ebp * NCOL + eh]);
            #pragma unroll
            for (int q = 1; q < 8; q++)
                sum = add2(sum,
                    __double_as_longlong(sm.part[cx][(q * 2 + ebp) * NCOL + eh]));
            float p0, p1;
            unpack2(sum, p0, p1);
            const float n0 = fmaf(arv, tanh_fast(p0 + biasv) - s0, s0);
            const float n1 = fmaf(arv, tanh_fast(p1 + biasv) - s1, s1);
            s0 = n0; s1 = n1;
            *(double*)((char*)&sm.s[nbuf][0] + (c0 + eh) * 16 + ebp * 8) =
                __longlong_as_double(packxy(n0, n1));

            asm volatile("bar.sync 1, 128;" ::: "memory");  // slice complete

            if (tid < CLUSTER_N) {
                if (tid == (int)rank) {
                    // local release: own-kq warps wait this barrier
                    mbar_arrive(mbase + (uint32_t)(nbuf * 8 + (int)rank) * 8u);
                } else {
                    asm volatile("fence.proxy.async.shared::cta;" ::: "memory");
                    const uint32_t src = sbase + (uint32_t)nbuf * 8192u
                                       + (uint32_t)c0 * 16u;
                    const uint32_t rmb = mbase
                                       + (uint32_t)(nbuf * 8 + (int)rank) * 8u;
                    bulk_copy_peer(mapa_u32(src, (uint32_t)tid), src,
                                   SLICE_BYTES, mapa_u32(rmb, (uint32_t)tid));
                }
            }
        }
    }

    // final state: each warp waits its slice of buffer T%3, then sync
    mbar_wait(mbase + (uint32_t)((T_STEPS % 3) * 8 + kq) * 8u,
              (((uint32_t)T_STEPS - 1u) / 3u) & 1u);
    __syncthreads();

    if (rank == 0) {
        const float* sf = (const float*)&sm.s[T_STEPS % 3][0];
        const int wid = tid >> 5, lane = tid & 31;
        for (int bo = wid; bo < NBATCH * O_OUT; bo += NTHREADS / 32) {
            const int b = bo / O_OUT, o = bo % O_OUT;
            float acc = 0.f;
            for (int k = lane; k < H_DIM; k += 32)
                acc += sf[k * 4 + b] * Rw[k * O_OUT + o];
            #pragma unroll
            for (int off = 16; off; off >>= 1)
                acc += __shfl_xor_sync(0xffffffffu, acc, off);
            if (lane == 0) outg[(gb0 + b) * O_OUT + o] = acc + Rb[o];
        }
    }
}

extern "C" void kernel_launch(void* const* d_in, const int* in_sizes, int n_in,
                              void* d_out, int out_size)
{
    const float* x    = (const float*)d_in[0];
    const float* ic   = (const float*)d_in[1];
    const float* Win  = (const float*)d_in[2];
    const float* Wrec = (const float*)d_in[3];
    const float* b    = (const float*)d_in[4];
    const float* tau  = (const float*)d_in[5];
    const float* Rw   = (const float*)d_in[6];
    const float* Rb   = (const float*)d_in[7];
    float* out = (float*)d_out;
    (void)in_sizes; (void)n_in; (void)out_size;

    ctrnn_scan<<<GRID, NTHREADS>>>(x, ic, Win, Wrec, b, tau, Rw, Rb, out);
}